// round 10
// baseline (speedup 1.0000x reference)
#include <cuda_runtime.h>
#include <cuda_bf16.h>

// Problem constants (fixed by reference)
#define NN    50000
#define EE    800000
#define D     128
#define HID   64
#define HEADS 2
#define GG    64
#define OUTD  10
#define NEG_SLOPE 0.2f

// ---------------- scratch (static device globals; no allocation) -------------
__device__ float g_feat[NN * D];        // layer features (agg output / next input)
__device__ float g_g[NN * D];           // GEMM output h = feat @ W
__device__ float g_als[NN * HEADS];     // per-node src attention logits
__device__ float g_ald[NN * HEADS];     // per-node dst attention logits
__device__ int   g_deg[NN];
__device__ int   g_off[NN + 1];
__device__ int   g_cursor[NN];
__device__ int   g_srcidx[EE];          // CSR-by-dst: source node per slot
__device__ int   g_dstidx[EE];          // CSR-by-dst: dest node per slot
__device__ float g_wbuf[EE * 2];        // per-slot softmax weights (head0, head1)
__device__ float g_pool[GG * D];
__device__ int   g_cnt[GG];

__device__ __forceinline__ float leaky(float x) {
    return x > 0.f ? x : NEG_SLOPE * x;
}

// ---------------- init: zero deg + pool in one launch -------------------------
__global__ void init_kernel() {
    int i = blockIdx.x * blockDim.x + threadIdx.x;
    if (i < NN) g_deg[i] = 0;
    if (i < GG * D) g_pool[i] = 0.f;
    if (i < GG) g_cnt[i] = 0;
}

// ---------------- CSR build (edge_index is int32 on device) -------------------
__global__ void count_kernel(const int* __restrict__ ei) {
    int e = blockIdx.x * blockDim.x + threadIdx.x;
    if (e < EE) {
        unsigned d = (unsigned)ei[EE + e];
        if (d < NN) atomicAdd(&g_deg[d], 1);
    }
}

__global__ void scan_kernel() {
    __shared__ int s[1024];
    int t = threadIdx.x;
    const int CH = (NN + 1023) / 1024;   // 49
    int base = t * CH;
    int sum = 0;
    for (int i = 0; i < CH; i++) {
        int idx = base + i;
        if (idx < NN) sum += g_deg[idx];
    }
    s[t] = sum;
    __syncthreads();
    for (int off = 1; off < 1024; off <<= 1) {
        int v = (t >= off) ? s[t - off] : 0;
        __syncthreads();
        s[t] += v;
        __syncthreads();
    }
    int run = (t == 0) ? 0 : s[t - 1];   // exclusive prefix of this chunk
    for (int i = 0; i < CH; i++) {
        int idx = base + i;
        if (idx < NN) {
            g_off[idx] = run;
            g_cursor[idx] = run;
            run += g_deg[idx];
        }
    }
    if (t == 1023) g_off[NN] = s[1023];
}

__global__ void scatter_kernel(const int* __restrict__ ei) {
    int e = blockIdx.x * blockDim.x + threadIdx.x;
    if (e < EE) {
        unsigned d = (unsigned)ei[EE + e];
        unsigned s = (unsigned)ei[e];
        if (d < NN && s < NN) {
            int p = atomicAdd(&g_cursor[d], 1);
            g_srcidx[p] = (int)s;
            g_dstidx[p] = (int)d;
        }
    }
}

// ---------------- GEMM + fused alpha ------------------------------------------
// 64x128 tile, 256 threads; each thread computes 8 rows x 4 cols. FFMA2 packs
// {even-k, odd-k} partial sums; final h = lo + hi (~1e-7 vs scalar). Alpha
// logits computed from the tile in the epilogue.
#define GT_M 64
__global__ __launch_bounds__(256, 2)
void gemm128_kernel(const float* __restrict__ x,
                    const float* __restrict__ W,
                    const float* __restrict__ a_s,
                    const float* __restrict__ a_d,
                    int use_x) {
    __shared__ float As[GT_M][D];               // 32 KB
    const float* __restrict__ A = use_x ? x : (const float*)g_feat;
    int tid = threadIdx.x;
    int row0 = blockIdx.x * GT_M;
    int nrows = NN - row0; if (nrows > GT_M) nrows = GT_M;

    for (int i = tid; i < GT_M * (D / 4); i += 256) {
        int r = i >> 5, k4 = i & 31;
        float4 v = make_float4(0.f, 0.f, 0.f, 0.f);
        if (r < nrows) v = ((const float4*)(A + (size_t)(row0 + r) * D))[k4];
        ((float4*)As[r])[k4] = v;
    }
    __syncthreads();

    int lane = tid & 31, wgrp = tid >> 5;
    int c0 = lane * 4;          // 4 output columns
    int r0 = wgrp * 8;          // 8 output rows

    unsigned long long acc[8][4];
#pragma unroll
    for (int r = 0; r < 8; r++)
#pragma unroll
        for (int j = 0; j < 4; j++) acc[r][j] = 0ULL;

#pragma unroll 2
    for (int k = 0; k < D; k += 2) {
        float4 w0 = __ldg((const float4*)(W + (size_t)k * D + c0));
        float4 w1 = __ldg((const float4*)(W + (size_t)(k + 1) * D + c0));
        unsigned long long wp0, wp1, wp2, wp3;
        asm("mov.b64 %0, {%1, %2};" : "=l"(wp0) : "f"(w0.x), "f"(w1.x));
        asm("mov.b64 %0, {%1, %2};" : "=l"(wp1) : "f"(w0.y), "f"(w1.y));
        asm("mov.b64 %0, {%1, %2};" : "=l"(wp2) : "f"(w0.z), "f"(w1.z));
        asm("mov.b64 %0, {%1, %2};" : "=l"(wp3) : "f"(w0.w), "f"(w1.w));
#pragma unroll
        for (int r = 0; r < 8; r++) {
            float2 a = *(const float2*)&As[r0 + r][k];   // warp-broadcast LDS.64
            unsigned long long av;
            asm("mov.b64 %0, {%1, %2};" : "=l"(av) : "f"(a.x), "f"(a.y));
            asm("fma.rn.f32x2 %0, %1, %2, %0;" : "+l"(acc[r][0]) : "l"(av), "l"(wp0));
            asm("fma.rn.f32x2 %0, %1, %2, %0;" : "+l"(acc[r][1]) : "l"(av), "l"(wp1));
            asm("fma.rn.f32x2 %0, %1, %2, %0;" : "+l"(acc[r][2]) : "l"(av), "l"(wp2));
            asm("fma.rn.f32x2 %0, %1, %2, %0;" : "+l"(acc[r][3]) : "l"(av), "l"(wp3));
        }
    }
    __syncthreads();                       // everyone done reading As

#pragma unroll
    for (int r = 0; r < 8; r++) {
        int rr = r0 + r;
        if (rr < nrows) {
            float4 hv;
            float lo, hi;
            asm("mov.b64 {%0, %1}, %2;" : "=f"(lo), "=f"(hi) : "l"(acc[r][0])); hv.x = lo + hi;
            asm("mov.b64 {%0, %1}, %2;" : "=f"(lo), "=f"(hi) : "l"(acc[r][1])); hv.y = lo + hi;
            asm("mov.b64 {%0, %1}, %2;" : "=f"(lo), "=f"(hi) : "l"(acc[r][2])); hv.z = lo + hi;
            asm("mov.b64 {%0, %1}, %2;" : "=f"(lo), "=f"(hi) : "l"(acc[r][3])); hv.w = lo + hi;
            *(float4*)(g_g + (size_t)(row0 + rr) * D + c0) = hv;
            *(float4*)&As[rr][c0] = hv;
        }
    }
    __syncthreads();

    // alpha: 4 threads per row (quarters of 32 cols). head0=q0,1 head1=q2,3
    int rr = tid >> 2, q = tid & 3;
    if (rr < nrows) {
        float ps = 0.f, pd = 0.f;
        int cb = q * 32;
#pragma unroll
        for (int i = 0; i < 32; i++) {
            int ie = (i + tid) & 31;          // staggered
            float h = As[rr][cb + ie];
            ps += h * __ldg(&a_s[cb + ie]);
            pd += h * __ldg(&a_d[cb + ie]);
        }
        ps += __shfl_down_sync(0xffffffffu, ps, 1);
        pd += __shfl_down_sync(0xffffffffu, pd, 1);
        if ((q & 1) == 0) {
            int head = q >> 1;
            g_als[(row0 + rr) * HEADS + head] = ps;
            g_ald[(row0 + rr) * HEADS + head] = pd;
        }
    }
}

// ---------------- edge-parallel softmax weights -------------------------------
__global__ void weight_kernel() {
    int j = blockIdx.x * blockDim.x + threadIdx.x;
    if (j >= EE) return;
    unsigned s = (unsigned)g_srcidx[j];
    unsigned d = (unsigned)g_dstidx[j];
    float2 w2 = make_float2(0.f, 0.f);
    if (s < NN && d < NN) {
        float2 as2 = *(const float2*)&g_als[s * HEADS];
        float2 ad2 = *(const float2*)&g_ald[d * HEADS];
        w2.x = __expf(leaky(as2.x + ad2.x));
        w2.y = __expf(leaky(as2.y + ad2.y));
    }
    ((float2*)g_wbuf)[j] = w2;
}

// ---------------- aggregation: one warp per node, 4-way pipelined -------------
// Each lane owns 4 channels of the 128-channel row. Four independent edge
// triples (srcidx, weight, full-row float4 gather) are issued per iteration
// into four accumulators -> MLP 4 on the gather path.
__global__ void agg_kernel(const float* __restrict__ bias) {
    int n = (blockIdx.x * blockDim.x + threadIdx.x) >> 5;
    int lane = threadIdx.x & 31;
    if (n >= NN) return;
    int head = lane >> 4;                 // lanes 0-15: head0, 16-31: head1

    int o0 = g_off[n], o1 = g_off[n + 1];

    float4 a0 = make_float4(0.f, 0.f, 0.f, 0.f);
    float4 a1 = a0, a2 = a0, a3 = a0;
    float d0 = 0.f, d1 = 0.f, d2 = 0.f, d3 = 0.f;

    const float2* __restrict__ wb = (const float2*)g_wbuf;
    int j = o0;
    for (; j + 3 < o1; j += 4) {
        int s0 = __ldg(&g_srcidx[j]);
        int s1 = __ldg(&g_srcidx[j + 1]);
        int s2 = __ldg(&g_srcidx[j + 2]);
        int s3 = __ldg(&g_srcidx[j + 3]);
        float2 w20 = __ldg(wb + j);
        float2 w21 = __ldg(wb + j + 1);
        float2 w22 = __ldg(wb + j + 2);
        float2 w23 = __ldg(wb + j + 3);
        float4 f0 = __ldg(((const float4*)(g_g + (size_t)s0 * D)) + lane);
        float4 f1 = __ldg(((const float4*)(g_g + (size_t)s1 * D)) + lane);
        float4 f2 = __ldg(((const float4*)(g_g + (size_t)s2 * D)) + lane);
        float4 f3 = __ldg(((const float4*)(g_g + (size_t)s3 * D)) + lane);
        float w0 = (head == 0) ? w20.x : w20.y;
        float w1 = (head == 0) ? w21.x : w21.y;
        float w2 = (head == 0) ? w22.x : w22.y;
        float w3 = (head == 0) ? w23.x : w23.y;
        a0.x += w0 * f0.x; a0.y += w0 * f0.y; a0.z += w0 * f0.z; a0.w += w0 * f0.w; d0 += w0;
        a1.x += w1 * f1.x; a1.y += w1 * f1.y; a1.z += w1 * f1.z; a1.w += w1 * f1.w; d1 += w1;
        a2.x += w2 * f2.x; a2.y += w2 * f2.y; a2.z += w2 * f2.z; a2.w += w2 * f2.w; d2 += w2;
        a3.x += w3 * f3.x; a3.y += w3 * f3.y; a3.z += w3 * f3.z; a3.w += w3 * f3.w; d3 += w3;
    }
    for (; j < o1; j++) {
        int s = __ldg(&g_srcidx[j]);
        float2 w2v = __ldg(wb + j);
        float w = (head == 0) ? w2v.x : w2v.y;
        float4 f = __ldg(((const float4*)(g_g + (size_t)s * D)) + lane);
        a0.x += w * f.x; a0.y += w * f.y; a0.z += w * f.z; a0.w += w * f.w; d0 += w;
    }
    {   // self-loop
        float2 av = *(const float2*)&g_als[n * HEADS];
        float2 dv = *(const float2*)&g_ald[n * HEADS];
        float e = (head == 0) ? leaky(av.x + dv.x) : leaky(av.y + dv.y);
        float w = __expf(e);
        float4 f = ((const float4*)(g_g + (size_t)n * D))[lane];
        a1.x += w * f.x; a1.y += w * f.y; a1.z += w * f.z; a1.w += w * f.w; d1 += w;
    }

    float4 acc;
    acc.x = (a0.x + a1.x) + (a2.x + a3.x);
    acc.y = (a0.y + a1.y) + (a2.y + a3.y);
    acc.z = (a0.z + a1.z) + (a2.z + a3.z);
    acc.w = (a0.w + a1.w) + (a2.w + a3.w);
    float denom = (d0 + d1) + (d2 + d3);

    float inv = 1.f / denom;
    float4 bb = __ldg(((const float4*)bias) + lane);
    float v0 = acc.x * inv + bb.x;
    float v1 = acc.y * inv + bb.y;
    float v2 = acc.z * inv + bb.z;
    float v3 = acc.w * inv + bb.w;
    float4 outv;
    outv.x = v0 > 0.f ? v0 : expm1f(v0);
    outv.y = v1 > 0.f ? v1 : expm1f(v1);
    outv.z = v2 > 0.f ? v2 : expm1f(v2);
    outv.w = v3 > 0.f ? v3 : expm1f(v3);
    ((float4*)(g_feat + (size_t)n * D))[lane] = outv;
}

// ---------------- mean pool: batch is SORTED -> run accumulation --------------
#define PCH 32
__global__ void pool_kernel(const int* __restrict__ batch) {
    int c = threadIdx.x;                    // 0..127 channel
    int b0 = blockIdx.x * PCH;
    if (b0 >= NN) return;
    int nend = b0 + PCH; if (nend > NN) nend = NN;
    int curg = __ldg(&batch[b0]);
    float racc = 0.f;
    int rcnt = 0;
    for (int nidx = b0; nidx < nend; nidx++) {
        int g = __ldg(&batch[nidx]);
        if (g != curg) {
            if ((unsigned)curg < GG) {
                atomicAdd(&g_pool[curg * D + c], racc);
                if (c == 0) atomicAdd(&g_cnt[curg], rcnt);
            }
            racc = 0.f; rcnt = 0; curg = g;
        }
        racc += g_feat[(size_t)nidx * D + c];
        rcnt++;
    }
    if ((unsigned)curg < GG) {
        atomicAdd(&g_pool[curg * D + c], racc);
        if (c == 0) atomicAdd(&g_cnt[curg], rcnt);
    }
}

// ---------------- head MLP ---------------------------------------------------
__global__ void head_kernel(const float* __restrict__ l1w, const float* __restrict__ l1b,
                            const float* __restrict__ l2w, const float* __restrict__ l2b,
                            float* __restrict__ out) {
    int gid = blockIdx.x;    // 0..63
    int t = threadIdx.x;     // 0..63
    __shared__ float mean[D];
    __shared__ float z[HID];
    float invc = 1.f / fmaxf((float)g_cnt[gid], 1.f);
    mean[t]      = g_pool[gid * D + t] * invc;
    mean[t + 64] = g_pool[gid * D + 64 + t] * invc;
    __syncthreads();
    float acc = l1b[t];
    for (int k = 0; k < D; k++) acc += mean[k] * l1w[k * HID + t];
    z[t] = fmaxf(acc, 0.f);
    __syncthreads();
    if (t < OUTD) {
        float o = l2b[t];
        for (int k = 0; k < HID; k++) o += z[k] * l2w[k * OUTD + t];
        out[gid * OUTD + t] = o;
    }
}

// ---------------- driver ------------------------------------------------------
extern "C" void kernel_launch(void* const* d_in, const int* in_sizes, int n_in,
                              void* d_out, int out_size) {
    const float* x     = (const float*)d_in[0];
    const int*   ei    = (const int*)d_in[1];     // int64 in reference -> int32 on device
    const int*   batch = (const int*)d_in[2];     // int64 in reference -> int32 on device
    const float* Wl[3] = { (const float*)d_in[3],  (const float*)d_in[7],  (const float*)d_in[11] };
    const float* As[3] = { (const float*)d_in[4],  (const float*)d_in[8],  (const float*)d_in[12] };
    const float* Ad[3] = { (const float*)d_in[5],  (const float*)d_in[9],  (const float*)d_in[13] };
    const float* Bl[3] = { (const float*)d_in[6],  (const float*)d_in[10], (const float*)d_in[14] };
    const float* l1w = (const float*)d_in[15];
    const float* l1b = (const float*)d_in[16];
    const float* l2w = (const float*)d_in[17];
    const float* l2b = (const float*)d_in[18];
    float* out = (float*)d_out;

    // CSR build (reused across all 3 layers)
    init_kernel<<<(NN + 255) / 256, 256>>>();
    count_kernel<<<(EE + 255) / 256, 256>>>(ei);
    scan_kernel<<<1, 1024>>>();
    scatter_kernel<<<(EE + 255) / 256, 256>>>(ei);

    const int gemm_blocks   = (NN + GT_M - 1) / GT_M;
    const int weight_blocks = (EE + 255) / 256;
    const int agg_blocks    = (NN * 32 + 255) / 256;

    for (int l = 0; l < 3; l++) {
        gemm128_kernel<<<gemm_blocks, 256>>>(x, Wl[l], As[l], Ad[l], (l == 0) ? 1 : 0);
        weight_kernel<<<weight_blocks, 256>>>();
        agg_kernel<<<agg_blocks, 256>>>(Bl[l]);
    }

    pool_kernel<<<(NN + PCH - 1) / PCH, D>>>(batch);
    head_kernel<<<GG, HID>>>(l1w, l1b, l2w, l2b, out);
}

// round 11
// speedup vs baseline: 1.0450x; 1.0450x over previous
#include <cuda_runtime.h>
#include <cuda_bf16.h>

// Problem constants (fixed by reference)
#define NN    50000
#define EE    800000
#define D     128
#define HID   64
#define HEADS 2
#define GG    64
#define OUTD  10
#define NEG_SLOPE 0.2f

// ---------------- scratch (static device globals; no allocation) -------------
// g_deg is zero at process start and re-zeroed by scan_kernel after each use,
// so count can always assume a zeroed deg array.
__device__ float g_feat[NN * D];        // layer features (agg output / next input)
__device__ float g_g[NN * D];           // GEMM output h = feat @ W
__device__ float g_als[NN * HEADS];     // per-node src attention logits
__device__ float g_ald[NN * HEADS];     // per-node dst attention logits
__device__ int   g_deg[NN];
__device__ int   g_off[NN + 1];
__device__ int   g_cursor[NN];
__device__ int   g_srcidx[EE];          // CSR-by-dst: source node per slot
__device__ int   g_dstidx[EE];          // CSR-by-dst: dest node per slot
__device__ float g_wbuf[EE * 2];        // per-slot softmax weights (head0, head1)
__device__ float g_pool[GG * D];
__device__ int   g_cnt[GG];

__device__ __forceinline__ float leaky(float x) {
    return x > 0.f ? x : NEG_SLOPE * x;
}

// ---------------- GEMM tile body (shared by fused and plain kernels) ----------
// 64x128 tile, 256 threads; each thread computes 8 rows x 4 cols. FFMA2 packs
// {even-k, odd-k} partial sums; final h = lo + hi (~1e-7 vs scalar). Alpha
// logits computed from the tile at the end.
#define GT_M 64
#define GEMM_BLOCKS ((NN + GT_M - 1) / GT_M)     // 782
#define COUNT_BLOCKS ((EE + 255) / 256)          // 3125

__device__ __forceinline__ void gemm_tile(float (*As)[D],
                                          const float* __restrict__ A,
                                          const float* __restrict__ W,
                                          const float* __restrict__ a_s,
                                          const float* __restrict__ a_d,
                                          int row0, int tid) {
    int nrows = NN - row0; if (nrows > GT_M) nrows = GT_M;

    for (int i = tid; i < GT_M * (D / 4); i += 256) {
        int r = i >> 5, k4 = i & 31;
        float4 v = make_float4(0.f, 0.f, 0.f, 0.f);
        if (r < nrows) v = ((const float4*)(A + (size_t)(row0 + r) * D))[k4];
        ((float4*)As[r])[k4] = v;
    }
    __syncthreads();

    int lane = tid & 31, wgrp = tid >> 5;
    int c0 = lane * 4;          // 4 output columns
    int r0 = wgrp * 8;          // 8 output rows

    unsigned long long acc[8][4];
#pragma unroll
    for (int r = 0; r < 8; r++)
#pragma unroll
        for (int j = 0; j < 4; j++) acc[r][j] = 0ULL;

#pragma unroll 2
    for (int k = 0; k < D; k += 2) {
        float4 w0 = __ldg((const float4*)(W + (size_t)k * D + c0));
        float4 w1 = __ldg((const float4*)(W + (size_t)(k + 1) * D + c0));
        unsigned long long wp0, wp1, wp2, wp3;
        asm("mov.b64 %0, {%1, %2};" : "=l"(wp0) : "f"(w0.x), "f"(w1.x));
        asm("mov.b64 %0, {%1, %2};" : "=l"(wp1) : "f"(w0.y), "f"(w1.y));
        asm("mov.b64 %0, {%1, %2};" : "=l"(wp2) : "f"(w0.z), "f"(w1.z));
        asm("mov.b64 %0, {%1, %2};" : "=l"(wp3) : "f"(w0.w), "f"(w1.w));
#pragma unroll
        for (int r = 0; r < 8; r++) {
            float2 a = *(const float2*)&As[r0 + r][k];   // warp-broadcast LDS.64
            unsigned long long av;
            asm("mov.b64 %0, {%1, %2};" : "=l"(av) : "f"(a.x), "f"(a.y));
            asm("fma.rn.f32x2 %0, %1, %2, %0;" : "+l"(acc[r][0]) : "l"(av), "l"(wp0));
            asm("fma.rn.f32x2 %0, %1, %2, %0;" : "+l"(acc[r][1]) : "l"(av), "l"(wp1));
            asm("fma.rn.f32x2 %0, %1, %2, %0;" : "+l"(acc[r][2]) : "l"(av), "l"(wp2));
            asm("fma.rn.f32x2 %0, %1, %2, %0;" : "+l"(acc[r][3]) : "l"(av), "l"(wp3));
        }
    }
    __syncthreads();                       // everyone done reading As

#pragma unroll
    for (int r = 0; r < 8; r++) {
        int rr = r0 + r;
        if (rr < nrows) {
            float4 hv;
            float lo, hi;
            asm("mov.b64 {%0, %1}, %2;" : "=f"(lo), "=f"(hi) : "l"(acc[r][0])); hv.x = lo + hi;
            asm("mov.b64 {%0, %1}, %2;" : "=f"(lo), "=f"(hi) : "l"(acc[r][1])); hv.y = lo + hi;
            asm("mov.b64 {%0, %1}, %2;" : "=f"(lo), "=f"(hi) : "l"(acc[r][2])); hv.z = lo + hi;
            asm("mov.b64 {%0, %1}, %2;" : "=f"(lo), "=f"(hi) : "l"(acc[r][3])); hv.w = lo + hi;
            *(float4*)(g_g + (size_t)(row0 + rr) * D + c0) = hv;
            *(float4*)&As[rr][c0] = hv;
        }
    }
    __syncthreads();

    // alpha: 4 threads per row (quarters of 32 cols). head0=q0,1 head1=q2,3
    int rr = tid >> 2, q = tid & 3;
    if (rr < nrows) {
        float ps = 0.f, pd = 0.f;
        int cb = q * 32;
#pragma unroll
        for (int i = 0; i < 32; i++) {
            int ie = (i + tid) & 31;          // staggered
            float h = As[rr][cb + ie];
            ps += h * __ldg(&a_s[cb + ie]);
            pd += h * __ldg(&a_d[cb + ie]);
        }
        ps += __shfl_down_sync(0xffffffffu, ps, 1);
        pd += __shfl_down_sync(0xffffffffu, pd, 1);
        if ((q & 1) == 0) {
            int head = q >> 1;
            g_als[(row0 + rr) * HEADS + head] = ps;
            g_ald[(row0 + rr) * HEADS + head] = pd;
        }
    }
}

// ---------------- fused: GEMM layer-1 + CSR degree count ----------------------
// GEMM1 (reads x) and edge counting are independent; one launch runs both.
__global__ __launch_bounds__(256, 2)
void gemm1_count_kernel(const float* __restrict__ x,
                        const float* __restrict__ W,
                        const float* __restrict__ a_s,
                        const float* __restrict__ a_d,
                        const int* __restrict__ ei) {
    __shared__ float As[GT_M][D];               // 32 KB
    if (blockIdx.x < GEMM_BLOCKS) {
        gemm_tile(As, x, W, a_s, a_d, blockIdx.x * GT_M, threadIdx.x);
    } else {
        int e = (blockIdx.x - GEMM_BLOCKS) * 256 + threadIdx.x;
        if (e < EE) {
            unsigned d = (unsigned)ei[EE + e];
            if (d < NN) atomicAdd(&g_deg[d], 1);
        }
    }
}

// ---------------- plain GEMM (layers 2,3) -------------------------------------
__global__ __launch_bounds__(256, 2)
void gemm128_kernel(const float* __restrict__ W,
                    const float* __restrict__ a_s,
                    const float* __restrict__ a_d) {
    __shared__ float As[GT_M][D];               // 32 KB
    gemm_tile(As, (const float*)g_feat, W, a_s, a_d, blockIdx.x * GT_M, threadIdx.x);
}

// ---------------- scan: prefix offsets; also re-zero deg/pool/cnt -------------
__global__ void scan_kernel() {
    __shared__ int s[1024];
    int t = threadIdx.x;
    const int CH = (NN + 1023) / 1024;   // 49
    int base = t * CH;
    int sum = 0;
    int degs[CH];
    for (int i = 0; i < CH; i++) {
        int idx = base + i;
        degs[i] = (idx < NN) ? g_deg[idx] : 0;
        sum += degs[i];
    }
    s[t] = sum;
    __syncthreads();
    for (int off = 1; off < 1024; off <<= 1) {
        int v = (t >= off) ? s[t - off] : 0;
        __syncthreads();
        s[t] += v;
        __syncthreads();
    }
    int run = (t == 0) ? 0 : s[t - 1];   // exclusive prefix of this chunk
    for (int i = 0; i < CH; i++) {
        int idx = base + i;
        if (idx < NN) {
            g_off[idx] = run;
            g_cursor[idx] = run;
            run += degs[i];
            g_deg[idx] = 0;              // restore invariant for next call
        }
    }
    if (t == 1023) g_off[NN] = s[1023];
    // zero pool accumulators (needed before pool_kernel later this call)
    for (int i = t; i < GG * D; i += 1024) g_pool[i] = 0.f;
    if (t < GG) g_cnt[t] = 0;
}

__global__ void scatter_kernel(const int* __restrict__ ei) {
    int e = blockIdx.x * blockDim.x + threadIdx.x;
    if (e < EE) {
        unsigned d = (unsigned)ei[EE + e];
        unsigned s = (unsigned)ei[e];
        if (d < NN && s < NN) {
            int p = atomicAdd(&g_cursor[d], 1);
            g_srcidx[p] = (int)s;
            g_dstidx[p] = (int)d;
        }
    }
}

// ---------------- edge-parallel softmax weights -------------------------------
__global__ void weight_kernel() {
    int j = blockIdx.x * blockDim.x + threadIdx.x;
    if (j >= EE) return;
    unsigned s = (unsigned)g_srcidx[j];
    unsigned d = (unsigned)g_dstidx[j];
    float2 w2 = make_float2(0.f, 0.f);
    if (s < NN && d < NN) {
        float2 as2 = *(const float2*)&g_als[s * HEADS];
        float2 ad2 = *(const float2*)&g_ald[d * HEADS];
        w2.x = __expf(leaky(as2.x + ad2.x));
        w2.y = __expf(leaky(as2.y + ad2.y));
    }
    ((float2*)g_wbuf)[j] = w2;
}

// ---------------- aggregation: one warp per node, both heads (R9 form) --------
// Each lane owns 4 channels of the full 128-channel row. Per edge: broadcast
// srcidx (prefetched) + broadcast weight pair (streaming) + ONE full-row
// float4 gather. Every lane accumulates its head's denom -> no reduction.
__global__ void agg_kernel(const float* __restrict__ bias) {
    int n = (blockIdx.x * blockDim.x + threadIdx.x) >> 5;
    int lane = threadIdx.x & 31;
    if (n >= NN) return;
    int head = lane >> 4;                 // lanes 0-15: head0, 16-31: head1

    int o0 = g_off[n], o1 = g_off[n + 1];

    float4 acc = make_float4(0.f, 0.f, 0.f, 0.f);
    float denom = 0.f;

    int sj = (o0 < o1) ? __ldg(&g_srcidx[o0]) : 0;
    for (int j = o0; j < o1; j++) {
        int s = sj;
        if (j + 1 < o1) sj = __ldg(&g_srcidx[j + 1]);          // prefetch
        float2 w2 = __ldg(((const float2*)g_wbuf) + j);        // streaming
        float w = (head == 0) ? w2.x : w2.y;
        float4 f = __ldg(((const float4*)(g_g + (size_t)s * D)) + lane);
        acc.x += w * f.x; acc.y += w * f.y; acc.z += w * f.z; acc.w += w * f.w;
        denom += w;
    }
    {   // self-loop
        float2 a2 = *(const float2*)&g_als[n * HEADS];
        float2 d2 = *(const float2*)&g_ald[n * HEADS];
        float e = (head == 0) ? leaky(a2.x + d2.x) : leaky(a2.y + d2.y);
        float w = __expf(e);
        float4 f = ((const float4*)(g_g + (size_t)n * D))[lane];
        acc.x += w * f.x; acc.y += w * f.y; acc.z += w * f.z; acc.w += w * f.w;
        denom += w;
    }

    float inv = 1.f / denom;
    float4 bb = __ldg(((const float4*)bias) + lane);
    float v0 = acc.x * inv + bb.x;
    float v1 = acc.y * inv + bb.y;
    float v2 = acc.z * inv + bb.z;
    float v3 = acc.w * inv + bb.w;
    float4 outv;
    outv.x = v0 > 0.f ? v0 : expm1f(v0);
    outv.y = v1 > 0.f ? v1 : expm1f(v1);
    outv.z = v2 > 0.f ? v2 : expm1f(v2);
    outv.w = v3 > 0.f ? v3 : expm1f(v3);
    ((float4*)(g_feat + (size_t)n * D))[lane] = outv;
}

// ---------------- mean pool: batch is SORTED -> run accumulation --------------
#define PCH 32
__global__ void pool_kernel(const int* __restrict__ batch) {
    int c = threadIdx.x;                    // 0..127 channel
    int b0 = blockIdx.x * PCH;
    if (b0 >= NN) return;
    int nend = b0 + PCH; if (nend > NN) nend = NN;
    int curg = __ldg(&batch[b0]);
    float racc = 0.f;
    int rcnt = 0;
    for (int nidx = b0; nidx < nend; nidx++) {
        int g = __ldg(&batch[nidx]);
        if (g != curg) {
            if ((unsigned)curg < GG) {
                atomicAdd(&g_pool[curg * D + c], racc);
                if (c == 0) atomicAdd(&g_cnt[curg], rcnt);
            }
            racc = 0.f; rcnt = 0; curg = g;
        }
        racc += g_feat[(size_t)nidx * D + c];
        rcnt++;
    }
    if ((unsigned)curg < GG) {
        atomicAdd(&g_pool[curg * D + c], racc);
        if (c == 0) atomicAdd(&g_cnt[curg], rcnt);
    }
}

// ---------------- head MLP ---------------------------------------------------
__global__ void head_kernel(const float* __restrict__ l1w, const float* __restrict__ l1b,
                            const float* __restrict__ l2w, const float* __restrict__ l2b,
                            float* __restrict__ out) {
    int gid = blockIdx.x;    // 0..63
    int t = threadIdx.x;     // 0..63
    __shared__ float mean[D];
    __shared__ float z[HID];
    float invc = 1.f / fmaxf((float)g_cnt[gid], 1.f);
    mean[t]      = g_pool[gid * D + t] * invc;
    mean[t + 64] = g_pool[gid * D + 64 + t] * invc;
    __syncthreads();
    float acc = l1b[t];
    for (int k = 0; k < D; k++) acc += mean[k] * l1w[k * HID + t];
    z[t] = fmaxf(acc, 0.f);
    __syncthreads();
    if (t < OUTD) {
        float o = l2b[t];
        for (int k = 0; k < HID; k++) o += z[k] * l2w[k * OUTD + t];
        out[gid * OUTD + t] = o;
    }
}

// ---------------- driver ------------------------------------------------------
extern "C" void kernel_launch(void* const* d_in, const int* in_sizes, int n_in,
                              void* d_out, int out_size) {
    const float* x     = (const float*)d_in[0];
    const int*   ei    = (const int*)d_in[1];     // int64 in reference -> int32 on device
    const int*   batch = (const int*)d_in[2];     // int64 in reference -> int32 on device
    const float* Wl[3] = { (const float*)d_in[3],  (const float*)d_in[7],  (const float*)d_in[11] };
    const float* As[3] = { (const float*)d_in[4],  (const float*)d_in[8],  (const float*)d_in[12] };
    const float* Ad[3] = { (const float*)d_in[5],  (const float*)d_in[9],  (const float*)d_in[13] };
    const float* Bl[3] = { (const float*)d_in[6],  (const float*)d_in[10], (const float*)d_in[14] };
    const float* l1w = (const float*)d_in[15];
    const float* l1b = (const float*)d_in[16];
    const float* l2w = (const float*)d_in[17];
    const float* l2b = (const float*)d_in[18];
    float* out = (float*)d_out;

    const int weight_blocks = (EE + 255) / 256;
    const int agg_blocks    = (NN * 32 + 255) / 256;

    // layer 1 GEMM runs fused with CSR degree count (independent work)
    gemm1_count_kernel<<<GEMM_BLOCKS + COUNT_BLOCKS, 256>>>(x, Wl[0], As[0], Ad[0], ei);
    scan_kernel<<<1, 1024>>>();
    scatter_kernel<<<(EE + 255) / 256, 256>>>(ei);

    weight_kernel<<<weight_blocks, 256>>>();
    agg_kernel<<<agg_blocks, 256>>>(Bl[0]);

    for (int l = 1; l < 3; l++) {
        gemm128_kernel<<<GEMM_BLOCKS, 256>>>(Wl[l], As[l], Ad[l]);
        weight_kernel<<<weight_blocks, 256>>>();
        agg_kernel<<<agg_blocks, 256>>>(Bl[l]);
    }

    pool_kernel<<<(NN + PCH - 1) / PCH, D>>>(batch);
    head_kernel<<<GG, HID>>>(l1w, l1b, l2w, l2b, out);
}

// round 12
// speedup vs baseline: 1.3474x; 1.2894x over previous
#include <cuda_runtime.h>
#include <cuda_bf16.h>
#include <cuda_fp16.h>

// Problem constants (fixed by reference)
#define NN    50000
#define EE    800000
#define D     128
#define HID   64
#define HEADS 2
#define GG    64
#define OUTD  10
#define NEG_SLOPE 0.2f

// ---------------- scratch (static device globals; no allocation) -------------
// g_deg is zero at process start and re-zeroed by offs_kernel after each use.
__device__ float   g_feat[NN * D];      // layer features (agg output / next input)
__device__ __half2 g_h[NN * (D / 2)];   // GEMM output h, fp16 (agg gather source)
__device__ float   g_als[NN * HEADS];   // per-node src attention logits
__device__ float   g_ald[NN * HEADS];   // per-node dst attention logits
__device__ int     g_deg[NN];
__device__ int     g_off[NN + 1];
__device__ int     g_cursor[NN];
__device__ int     g_srcidx[EE];        // CSR-by-dst: source node per slot
__device__ int     g_dstidx[EE];        // CSR-by-dst: dest node per slot
__device__ float   g_wbuf[EE * 2];      // per-slot softmax weights (head0, head1)
__device__ float   g_pool[GG * D];
__device__ int     g_cnt[GG];

#define SB 256
#define NB ((NN + SB - 1) / SB)         // 196
__device__ int g_bsum[NB];
__device__ int g_bbase[NB];

__device__ __forceinline__ float leaky(float x) {
    return x > 0.f ? x : NEG_SLOPE * x;
}

// ---------------- GEMM tile body ----------------------------------------------
// 64x128 tile, 256 threads; each thread computes 8 rows x 4 cols. FFMA2 packs
// {even-k, odd-k} partial sums; final h = lo + hi (~1e-7 vs scalar). Writes h
// as fp16 to g_h; alpha logits computed fp32 from the smem tile.
#define GT_M 64
#define GEMM_BLOCKS ((NN + GT_M - 1) / GT_M)     // 782
#define COUNT_BLOCKS ((EE + 255) / 256)          // 3125

__device__ __forceinline__ void gemm_tile(float (*As)[D],
                                          const float* __restrict__ A,
                                          const float* __restrict__ W,
                                          const float* __restrict__ a_s,
                                          const float* __restrict__ a_d,
                                          int row0, int tid) {
    int nrows = NN - row0; if (nrows > GT_M) nrows = GT_M;

    for (int i = tid; i < GT_M * (D / 4); i += 256) {
        int r = i >> 5, k4 = i & 31;
        float4 v = make_float4(0.f, 0.f, 0.f, 0.f);
        if (r < nrows) v = ((const float4*)(A + (size_t)(row0 + r) * D))[k4];
        ((float4*)As[r])[k4] = v;
    }
    __syncthreads();

    int lane = tid & 31, wgrp = tid >> 5;
    int c0 = lane * 4;          // 4 output columns
    int r0 = wgrp * 8;          // 8 output rows

    unsigned long long acc[8][4];
#pragma unroll
    for (int r = 0; r < 8; r++)
#pragma unroll
        for (int j = 0; j < 4; j++) acc[r][j] = 0ULL;

#pragma unroll 2
    for (int k = 0; k < D; k += 2) {
        float4 w0 = __ldg((const float4*)(W + (size_t)k * D + c0));
        float4 w1 = __ldg((const float4*)(W + (size_t)(k + 1) * D + c0));
        unsigned long long wp0, wp1, wp2, wp3;
        asm("mov.b64 %0, {%1, %2};" : "=l"(wp0) : "f"(w0.x), "f"(w1.x));
        asm("mov.b64 %0, {%1, %2};" : "=l"(wp1) : "f"(w0.y), "f"(w1.y));
        asm("mov.b64 %0, {%1, %2};" : "=l"(wp2) : "f"(w0.z), "f"(w1.z));
        asm("mov.b64 %0, {%1, %2};" : "=l"(wp3) : "f"(w0.w), "f"(w1.w));
#pragma unroll
        for (int r = 0; r < 8; r++) {
            float2 a = *(const float2*)&As[r0 + r][k];   // warp-broadcast LDS.64
            unsigned long long av;
            asm("mov.b64 %0, {%1, %2};" : "=l"(av) : "f"(a.x), "f"(a.y));
            asm("fma.rn.f32x2 %0, %1, %2, %0;" : "+l"(acc[r][0]) : "l"(av), "l"(wp0));
            asm("fma.rn.f32x2 %0, %1, %2, %0;" : "+l"(acc[r][1]) : "l"(av), "l"(wp1));
            asm("fma.rn.f32x2 %0, %1, %2, %0;" : "+l"(acc[r][2]) : "l"(av), "l"(wp2));
            asm("fma.rn.f32x2 %0, %1, %2, %0;" : "+l"(acc[r][3]) : "l"(av), "l"(wp3));
        }
    }
    __syncthreads();                       // everyone done reading As

#pragma unroll
    for (int r = 0; r < 8; r++) {
        int rr = r0 + r;
        if (rr < nrows) {
            float4 hv;
            float lo, hi;
            asm("mov.b64 {%0, %1}, %2;" : "=f"(lo), "=f"(hi) : "l"(acc[r][0])); hv.x = lo + hi;
            asm("mov.b64 {%0, %1}, %2;" : "=f"(lo), "=f"(hi) : "l"(acc[r][1])); hv.y = lo + hi;
            asm("mov.b64 {%0, %1}, %2;" : "=f"(lo), "=f"(hi) : "l"(acc[r][2])); hv.z = lo + hi;
            asm("mov.b64 {%0, %1}, %2;" : "=f"(lo), "=f"(hi) : "l"(acc[r][3])); hv.w = lo + hi;
            *(float4*)&As[rr][c0] = hv;
            __half2 p0 = __floats2half2_rn(hv.x, hv.y);
            __half2 p1 = __floats2half2_rn(hv.z, hv.w);
            uint2 u = make_uint2(*(unsigned*)&p0, *(unsigned*)&p1);
            *(uint2*)&g_h[(size_t)(row0 + rr) * (D / 2) + lane * 2] = u;
        }
    }
    __syncthreads();

    // alpha: 4 threads per row (quarters of 32 cols). head0=q0,1 head1=q2,3
    int rr = tid >> 2, q = tid & 3;
    if (rr < nrows) {
        float ps = 0.f, pd = 0.f;
        int cb = q * 32;
#pragma unroll
        for (int i = 0; i < 32; i++) {
            int ie = (i + tid) & 31;          // staggered
            float h = As[rr][cb + ie];
            ps += h * __ldg(&a_s[cb + ie]);
            pd += h * __ldg(&a_d[cb + ie]);
        }
        ps += __shfl_down_sync(0xffffffffu, ps, 1);
        pd += __shfl_down_sync(0xffffffffu, pd, 1);
        if ((q & 1) == 0) {
            int head = q >> 1;
            g_als[(row0 + rr) * HEADS + head] = ps;
            g_ald[(row0 + rr) * HEADS + head] = pd;
        }
    }
}

// ---------------- fused: GEMM layer-1 + CSR degree count ----------------------
__global__ __launch_bounds__(256, 2)
void gemm1_count_kernel(const float* __restrict__ x,
                        const float* __restrict__ W,
                        const float* __restrict__ a_s,
                        const float* __restrict__ a_d,
                        const int* __restrict__ ei) {
    __shared__ float As[GT_M][D];               // 32 KB
    if (blockIdx.x < GEMM_BLOCKS) {
        gemm_tile(As, x, W, a_s, a_d, blockIdx.x * GT_M, threadIdx.x);
    } else {
        int e = (blockIdx.x - GEMM_BLOCKS) * 256 + threadIdx.x;
        if (e < EE) {
            unsigned d = (unsigned)ei[EE + e];
            if (d < NN) atomicAdd(&g_deg[d], 1);
        }
    }
}

// ---------------- plain GEMM (layers 2,3) -------------------------------------
__global__ __launch_bounds__(256, 2)
void gemm128_kernel(const float* __restrict__ W,
                    const float* __restrict__ a_s,
                    const float* __restrict__ a_d) {
    __shared__ float As[GT_M][D];               // 32 KB
    gemm_tile(As, (const float*)g_feat, W, a_s, a_d, blockIdx.x * GT_M, threadIdx.x);
}

// ---------------- parallel CSR scan (3 small kernels) --------------------------
__global__ void bsum_kernel() {                  // NB blocks x 256
    __shared__ int sh[SB];
    int t = threadIdx.x;
    int i = blockIdx.x * SB + t;
    sh[t] = (i < NN) ? g_deg[i] : 0;
    __syncthreads();
    for (int o = SB / 2; o; o >>= 1) {
        if (t < o) sh[t] += sh[t + o];
        __syncthreads();
    }
    if (t == 0) g_bsum[blockIdx.x] = sh[0];
}

__global__ void bscan_kernel() {                 // 1 block x 256
    __shared__ int sh[SB];
    int t = threadIdx.x;
    int v = (t < NB) ? g_bsum[t] : 0;
    sh[t] = v;
    __syncthreads();
    for (int o = 1; o < SB; o <<= 1) {
        int u = (t >= o) ? sh[t - o] : 0;
        __syncthreads();
        sh[t] += u;
        __syncthreads();
    }
    if (t < NB) g_bbase[t] = sh[t] - v;          // exclusive
    if (t == SB - 1) g_off[NN] = sh[SB - 1];
    for (int i = t; i < GG * D; i += SB) g_pool[i] = 0.f;
    if (t < GG) g_cnt[t] = 0;
}

__global__ void offs_kernel() {                  // NB blocks x 256
    __shared__ int sh[SB];
    int t = threadIdx.x;
    int i = blockIdx.x * SB + t;
    int v = (i < NN) ? g_deg[i] : 0;
    sh[t] = v;
    __syncthreads();
    for (int o = 1; o < SB; o <<= 1) {
        int u = (t >= o) ? sh[t - o] : 0;
        __syncthreads();
        sh[t] += u;
        __syncthreads();
    }
    if (i < NN) {
        int off = g_bbase[blockIdx.x] + sh[t] - v;
        g_off[i] = off;
        g_cursor[i] = off;
        g_deg[i] = 0;                            // restore invariant
    }
}

__global__ void scatter_kernel(const int* __restrict__ ei) {
    int e = blockIdx.x * blockDim.x + threadIdx.x;
    if (e < EE) {
        unsigned d = (unsigned)ei[EE + e];
        unsigned s = (unsigned)ei[e];
        if (d < NN && s < NN) {
            int p = atomicAdd(&g_cursor[d], 1);
            g_srcidx[p] = (int)s;
            g_dstidx[p] = (int)d;
        }
    }
}

// ---------------- edge-parallel softmax weights -------------------------------
__global__ void weight_kernel() {
    int j = blockIdx.x * blockDim.x + threadIdx.x;
    if (j >= EE) return;
    unsigned s = (unsigned)g_srcidx[j];
    unsigned d = (unsigned)g_dstidx[j];
    float2 w2 = make_float2(0.f, 0.f);
    if (s < NN && d < NN) {
        float2 as2 = *(const float2*)&g_als[s * HEADS];
        float2 ad2 = *(const float2*)&g_ald[d * HEADS];
        w2.x = __expf(leaky(as2.x + ad2.x));
        w2.y = __expf(leaky(as2.y + ad2.y));
    }
    ((float2*)g_wbuf)[j] = w2;
}

// ---------------- aggregation: one warp per node (R9 form, fp16 gathers) ------
// Each lane owns 4 channels (one uint2 = 2x half2 = 8 B; full row = 256 B).
// fp32 accumulation; weights/logits fp32.
__global__ void agg_kernel(const float* __restrict__ bias) {
    int n = (blockIdx.x * blockDim.x + threadIdx.x) >> 5;
    int lane = threadIdx.x & 31;
    if (n >= NN) return;
    int head = lane >> 4;                 // lanes 0-15: head0, 16-31: head1

    int o0 = g_off[n], o1 = g_off[n + 1];

    float4 acc = make_float4(0.f, 0.f, 0.f, 0.f);
    float denom = 0.f;

    int sj = (o0 < o1) ? __ldg(&g_srcidx[o0]) : 0;
    for (int j = o0; j < o1; j++) {
        int s = sj;
        if (j + 1 < o1) sj = __ldg(&g_srcidx[j + 1]);          // prefetch
        float2 w2 = __ldg(((const float2*)g_wbuf) + j);        // streaming
        float w = (head == 0) ? w2.x : w2.y;
        uint2 u = __ldg(((const uint2*)(g_h + (size_t)s * (D / 2))) + lane);
        float2 f01 = __half22float2(*(__half2*)&u.x);
        float2 f23 = __half22float2(*(__half2*)&u.y);
        acc.x += w * f01.x; acc.y += w * f01.y; acc.z += w * f23.x; acc.w += w * f23.y;
        denom += w;
    }
    {   // self-loop
        float2 a2 = *(const float2*)&g_als[n * HEADS];
        float2 d2 = *(const float2*)&g_ald[n * HEADS];
        float e = (head == 0) ? leaky(a2.x + d2.x) : leaky(a2.y + d2.y);
        float w = __expf(e);
        uint2 u = ((const uint2*)(g_h + (size_t)n * (D / 2)))[lane];
        float2 f01 = __half22float2(*(__half2*)&u.x);
        float2 f23 = __half22float2(*(__half2*)&u.y);
        acc.x += w * f01.x; acc.y += w * f01.y; acc.z += w * f23.x; acc.w += w * f23.y;
        denom += w;
    }

    float inv = 1.f / denom;
    float4 bb = __ldg(((const float4*)bias) + lane);
    float v0 = acc.x * inv + bb.x;
    float v1 = acc.y * inv + bb.y;
    float v2 = acc.z * inv + bb.z;
    float v3 = acc.w * inv + bb.w;
    float4 outv;
    outv.x = v0 > 0.f ? v0 : expm1f(v0);
    outv.y = v1 > 0.f ? v1 : expm1f(v1);
    outv.z = v2 > 0.f ? v2 : expm1f(v2);
    outv.w = v3 > 0.f ? v3 : expm1f(v3);
    ((float4*)(g_feat + (size_t)n * D))[lane] = outv;
}

// ---------------- mean pool: batch is SORTED -> run accumulation --------------
#define PCH 32
__global__ void pool_kernel(const int* __restrict__ batch) {
    int c = threadIdx.x;                    // 0..127 channel
    int b0 = blockIdx.x * PCH;
    if (b0 >= NN) return;
    int nend = b0 + PCH; if (nend > NN) nend = NN;
    int curg = __ldg(&batch[b0]);
    float racc = 0.f;
    int rcnt = 0;
    for (int nidx = b0; nidx < nend; nidx++) {
        int g = __ldg(&batch[nidx]);
        if (g != curg) {
            if ((unsigned)curg < GG) {
                atomicAdd(&g_pool[curg * D + c], racc);
                if (c == 0) atomicAdd(&g_cnt[curg], rcnt);
            }
            racc = 0.f; rcnt = 0; curg = g;
        }
        racc += g_feat[(size_t)nidx * D + c];
        rcnt++;
    }
    if ((unsigned)curg < GG) {
        atomicAdd(&g_pool[curg * D + c], racc);
        if (c == 0) atomicAdd(&g_cnt[curg], rcnt);
    }
}

// ---------------- head MLP ---------------------------------------------------
__global__ void head_kernel(const float* __restrict__ l1w, const float* __restrict__ l1b,
                            const float* __restrict__ l2w, const float* __restrict__ l2b,
                            float* __restrict__ out) {
    int gid = blockIdx.x;    // 0..63
    int t = threadIdx.x;     // 0..63
    __shared__ float mean[D];
    __shared__ float z[HID];
    float invc = 1.f / fmaxf((float)g_cnt[gid], 1.f);
    mean[t]      = g_pool[gid * D + t] * invc;
    mean[t + 64] = g_pool[gid * D + 64 + t] * invc;
    __syncthreads();
    float acc = l1b[t];
    for (int k = 0; k < D; k++) acc += mean[k] * l1w[k * HID + t];
    z[t] = fmaxf(acc, 0.f);
    __syncthreads();
    if (t < OUTD) {
        float o = l2b[t];
        for (int k = 0; k < HID; k++) o += z[k] * l2w[k * OUTD + t];
        out[gid * OUTD + t] = o;
    }
}

// ---------------- driver ------------------------------------------------------
extern "C" void kernel_launch(void* const* d_in, const int* in_sizes, int n_in,
                              void* d_out, int out_size) {
    const float* x     = (const float*)d_in[0];
    const int*   ei    = (const int*)d_in[1];     // int64 in reference -> int32 on device
    const int*   batch = (const int*)d_in[2];     // int64 in reference -> int32 on device
    const float* Wl[3] = { (const float*)d_in[3],  (const float*)d_in[7],  (const float*)d_in[11] };
    const float* As[3] = { (const float*)d_in[4],  (const float*)d_in[8],  (const float*)d_in[12] };
    const float* Ad[3] = { (const float*)d_in[5],  (const float*)d_in[9],  (const float*)d_in[13] };
    const float* Bl[3] = { (const float*)d_in[6],  (const float*)d_in[10], (const float*)d_in[14] };
    const float* l1w = (const float*)d_in[15];
    const float* l1b = (const float*)d_in[16];
    const float* l2w = (const float*)d_in[17];
    const float* l2b = (const float*)d_in[18];
    float* out = (float*)d_out;

    const int weight_blocks = (EE + 255) / 256;
    const int agg_blocks    = (NN * 32 + 255) / 256;

    // layer 1 GEMM runs fused with CSR degree count (independent work)
    gemm1_count_kernel<<<GEMM_BLOCKS + COUNT_BLOCKS, 256>>>(x, Wl[0], As[0], Ad[0], ei);
    bsum_kernel<<<NB, SB>>>();
    bscan_kernel<<<1, SB>>>();
    offs_kernel<<<NB, SB>>>();
    scatter_kernel<<<(EE + 255) / 256, 256>>>(ei);

    weight_kernel<<<weight_blocks, 256>>>();
    agg_kernel<<<agg_blocks, 256>>>(Bl[0]);

    for (int l = 1; l < 3; l++) {
        gemm128_kernel<<<GEMM_BLOCKS, 256>>>(Wl[l], As[l], Ad[l]);
        weight_kernel<<<weight_blocks, 256>>>();
        agg_kernel<<<agg_blocks, 256>>>(Bl[l]);
    }

    pool_kernel<<<(NN + PCH - 1) / PCH, D>>>(batch);
    head_kernel<<<GG, HID>>>(l1w, l1b, l2w, l2b, out);
}

// round 13
// speedup vs baseline: 1.9709x; 1.4628x over previous
#include <cuda_runtime.h>
#include <cuda_bf16.h>
#include <cuda_fp16.h>

// Problem constants (fixed by reference)
#define NN    50000
#define EE    800000
#define D     128
#define HID   64
#define HEADS 2
#define GG    64
#define OUTD  10
#define NEG_SLOPE 0.2f

// ---------------- scratch (static device globals; no allocation) -------------
// g_deg is zero at process start and re-zeroed by offs_kernel after each use.
__device__ float   g_feat[NN * D];      // layer features fp32 (pool input)
__device__ __half  g_featH[NN * D];     // layer features fp16 (next GEMM input)
__device__ __half  g_xh[NN * D];        // x converted to fp16 (layer-1 GEMM input)
__device__ __half  g_wh[3 * D * D];     // weights fp16, TRANSPOSED [c][k], per layer
__device__ __half2 g_h[NN * (D / 2)];   // GEMM output h, fp16 (agg gather source)
__device__ float   g_als[NN * HEADS];   // per-node src attention logits
__device__ float   g_ald[NN * HEADS];   // per-node dst attention logits
__device__ int     g_deg[NN];
__device__ int     g_off[NN + 1];
__device__ int     g_cursor[NN];
__device__ int     g_srcidx[EE];        // CSR-by-dst: source node per slot
__device__ int     g_dstidx[EE];        // CSR-by-dst: dest node per slot
__device__ float   g_wbuf[EE * 2];      // per-slot softmax weights (head0, head1)
__device__ float   g_pool[GG * D];
__device__ int     g_cnt[GG];

#define SB 256
#define NB ((NN + SB - 1) / SB)         // 196
__device__ int g_bsum[NB];
__device__ int g_bbase[NB];

__device__ __forceinline__ float leaky(float x) {
    return x > 0.f ? x : NEG_SLOPE * x;
}

#define GT_M 64
#define GEMM_BLOCKS ((NN + GT_M - 1) / GT_M)          // 782
#define COUNT_BLOCKS ((EE + 255) / 256)               // 3125
#define XCONV_BLOCKS ((NN * D / 4 + 255) / 256)       // 6250

// ---------------- prep: W fp16-transpose x3 + x->fp16 + degree count ----------
__global__ void prep_kernel(const float* __restrict__ x,
                            const float* __restrict__ W1,
                            const float* __restrict__ W2,
                            const float* __restrict__ W3,
                            const int* __restrict__ ei) {
    __shared__ __half sh[D * 129];
    int b = blockIdx.x, tid = threadIdx.x;
    if (b < 3) {
        const float* Wp = (b == 0) ? W1 : (b == 1) ? W2 : W3;
        for (int i = tid; i < D * D; i += 256) {
            int k = i >> 7, c = i & 127;
            sh[k * 129 + c] = __float2half(Wp[i]);       // coalesced read
        }
        __syncthreads();
        for (int i = tid; i < D * D; i += 256) {
            int c = i >> 7, k = i & 127;
            g_wh[b * D * D + c * D + k] = sh[k * 129 + c];  // coalesced write
        }
    } else if (b < 3 + XCONV_BLOCKS) {
        int j = (b - 3) * 256 + tid;
        if (j < NN * D / 4) {
            float4 v = ((const float4*)x)[j];
            __half2 q0 = __floats2half2_rn(v.x, v.y);
            __half2 q1 = __floats2half2_rn(v.z, v.w);
            uint2 u = make_uint2(*(unsigned*)&q0, *(unsigned*)&q1);
            ((uint2*)g_xh)[j] = u;
        }
    } else {
        int e = (b - 3 - XCONV_BLOCKS) * 256 + tid;
        if (e < EE) {
            unsigned d = (unsigned)ei[EE + e];
            if (d < NN) atomicAdd(&g_deg[d], 1);
        }
    }
}

// ---------------- tensor-core GEMM + fused alpha -------------------------------
// 64x128 tile, 256 threads = 8 warps; mma.m16n8k16 f16*f16->f32.
// Warp w: m-tile (w&3)*16, n-half (w>>2)*64 (8 n-tiles of 8).
// A frags via guarded LDG from fp16 features; B frags from padded smem Wt
// (bank-free: uint bank = (4n + t) % 32). Accumulators staged to smem fp32
// for the alpha epilogue and fp16 h write.
#define WLD 136
__global__ __launch_bounds__(256)
void gemm_mma_kernel(const float* __restrict__ a_s,
                     const float* __restrict__ a_d,
                     int layer) {
    __shared__ __align__(16) unsigned char smraw[D * WLD * 2];   // 34816 B
    __half* wt = (__half*)smraw;
    float (*hf)[D] = (float(*)[D])smraw;                          // overlay (32768 B)

    int tid = threadIdx.x;
    int row0 = blockIdx.x * GT_M;
    int nrows = NN - row0; if (nrows > GT_M) nrows = GT_M;
    const __half* __restrict__ Ah = (layer == 0) ? (const __half*)g_xh
                                                 : (const __half*)g_featH;
    const __half* __restrict__ Wg = g_wh + layer * (D * D);

    // stage Wt: g_wh[c][k] (contiguous k) -> wt[c*WLD + k]
    {
        const unsigned* src = (const unsigned*)Wg;
        for (int i = tid; i < D * (D / 2); i += 256) {   // 8192 uints
            int c = i >> 6, ku = i & 63;
            *(unsigned*)&wt[c * WLD + ku * 2] = src[c * 64 + ku];
        }
    }
    __syncthreads();

    int lane = tid & 31, w = tid >> 5;
    int g = lane >> 2, t = lane & 3;
    int mt = (w & 3) * 16;
    int n0 = (w >> 2) * 64;

    int rLo = row0 + mt + g;
    int rHi = rLo + 8;
    bool okLo = rLo < NN, okHi = rHi < NN;
    const __half* pLo = Ah + (size_t)(okLo ? rLo : 0) * D + 2 * t;
    const __half* pHi = Ah + (size_t)(okHi ? rHi : 0) * D + 2 * t;

    float c_[8][4];
#pragma unroll
    for (int nt = 0; nt < 8; nt++)
#pragma unroll
        for (int j = 0; j < 4; j++) c_[nt][j] = 0.f;

#pragma unroll
    for (int k0 = 0; k0 < D; k0 += 16) {
        unsigned a0 = okLo ? *(const unsigned*)(pLo + k0)     : 0u;
        unsigned a1 = okHi ? *(const unsigned*)(pHi + k0)     : 0u;
        unsigned a2 = okLo ? *(const unsigned*)(pLo + k0 + 8) : 0u;
        unsigned a3 = okHi ? *(const unsigned*)(pHi + k0 + 8) : 0u;
#pragma unroll
        for (int nt = 0; nt < 8; nt++) {
            int n = n0 + nt * 8 + g;
            unsigned b0 = *(const unsigned*)&wt[n * WLD + k0 + 2 * t];
            unsigned b1 = *(const unsigned*)&wt[n * WLD + k0 + 2 * t + 8];
            asm volatile(
                "mma.sync.aligned.m16n8k16.row.col.f32.f16.f16.f32 "
                "{%0,%1,%2,%3}, {%4,%5,%6,%7}, {%8,%9}, {%0,%1,%2,%3};"
                : "+f"(c_[nt][0]), "+f"(c_[nt][1]), "+f"(c_[nt][2]), "+f"(c_[nt][3])
                : "r"(a0), "r"(a1), "r"(a2), "r"(a3), "r"(b0), "r"(b1));
        }
    }
    __syncthreads();                      // all wt reads done before hf overwrite

    // C frags -> smem fp32 tile (c0,c1: row g cols 2t,2t+1; c2,c3: row g+8)
#pragma unroll
    for (int nt = 0; nt < 8; nt++) {
        int n = n0 + nt * 8 + 2 * t;
        if (mt + g < nrows)
            *(float2*)&hf[mt + g][n] = make_float2(c_[nt][0], c_[nt][1]);
        if (mt + g + 8 < nrows)
            *(float2*)&hf[mt + g + 8][n] = make_float2(c_[nt][2], c_[nt][3]);
    }
    __syncthreads();

    // fp16 h write (agg gather source)
    for (int i = tid; i < GT_M * (D / 4); i += 256) {
        int r = i >> 5, c4 = i & 31;
        if (r < nrows) {
            float4 hv = *(float4*)&hf[r][c4 * 4];
            __half2 q0 = __floats2half2_rn(hv.x, hv.y);
            __half2 q1 = __floats2half2_rn(hv.z, hv.w);
            uint2 u = make_uint2(*(unsigned*)&q0, *(unsigned*)&q1);
            *(uint2*)&g_h[(size_t)(row0 + r) * (D / 2) + c4 * 2] = u;
        }
    }

    // alpha: 4 threads per row (quarters of 32 cols). head0=q0,1 head1=q2,3
    int rr = tid >> 2, q = tid & 3;
    if (rr < nrows) {
        float ps = 0.f, pd = 0.f;
        int cb = q * 32;
#pragma unroll
        for (int i = 0; i < 32; i++) {
            int ie = (i + tid) & 31;          // staggered
            float h = hf[rr][cb + ie];
            ps += h * __ldg(&a_s[cb + ie]);
            pd += h * __ldg(&a_d[cb + ie]);
        }
        ps += __shfl_down_sync(0xffffffffu, ps, 1);
        pd += __shfl_down_sync(0xffffffffu, pd, 1);
        if ((q & 1) == 0) {
            int head = q >> 1;
            g_als[(row0 + rr) * HEADS + head] = ps;
            g_ald[(row0 + rr) * HEADS + head] = pd;
        }
    }
}

// ---------------- parallel CSR scan (3 small kernels) --------------------------
__global__ void bsum_kernel() {                  // NB blocks x 256
    __shared__ int sh[SB];
    int t = threadIdx.x;
    int i = blockIdx.x * SB + t;
    sh[t] = (i < NN) ? g_deg[i] : 0;
    __syncthreads();
    for (int o = SB / 2; o; o >>= 1) {
        if (t < o) sh[t] += sh[t + o];
        __syncthreads();
    }
    if (t == 0) g_bsum[blockIdx.x] = sh[0];
}

__global__ void bscan_kernel() {                 // 1 block x 256
    __shared__ int sh[SB];
    int t = threadIdx.x;
    int v = (t < NB) ? g_bsum[t] : 0;
    sh[t] = v;
    __syncthreads();
    for (int o = 1; o < SB; o <<= 1) {
        int u = (t >= o) ? sh[t - o] : 0;
        __syncthreads();
        sh[t] += u;
        __syncthreads();
    }
    if (t < NB) g_bbase[t] = sh[t] - v;          // exclusive
    if (t == SB - 1) g_off[NN] = sh[SB - 1];
    for (int i = t; i < GG * D; i += SB) g_pool[i] = 0.f;
    if (t < GG) g_cnt[t] = 0;
}

__global__ void offs_kernel() {                  // NB blocks x 256
    __shared__ int sh[SB];
    int t = threadIdx.x;
    int i = blockIdx.x * SB + t;
    int v = (i < NN) ? g_deg[i] : 0;
    sh[t] = v;
    __syncthreads();
    for (int o = 1; o < SB; o <<= 1) {
        int u = (t >= o) ? sh[t - o] : 0;
        __syncthreads();
        sh[t] += u;
        __syncthreads();
    }
    if (i < NN) {
        int off = g_bbase[blockIdx.x] + sh[t] - v;
        g_off[i] = off;
        g_cursor[i] = off;
        g_deg[i] = 0;                            // restore invariant
    }
}

__global__ void scatter_kernel(const int* __restrict__ ei) {
    int e = blockIdx.x * blockDim.x + threadIdx.x;
    if (e < EE) {
        unsigned d = (unsigned)ei[EE + e];
        unsigned s = (unsigned)ei[e];
        if (d < NN && s < NN) {
            int p = atomicAdd(&g_cursor[d], 1);
            g_srcidx[p] = (int)s;
            g_dstidx[p] = (int)d;
        }
    }
}

// ---------------- edge-parallel softmax weights -------------------------------
__global__ void weight_kernel() {
    int j = blockIdx.x * blockDim.x + threadIdx.x;
    if (j >= EE) return;
    unsigned s = (unsigned)g_srcidx[j];
    unsigned d = (unsigned)g_dstidx[j];
    float2 w2 = make_float2(0.f, 0.f);
    if (s < NN && d < NN) {
        float2 as2 = *(const float2*)&g_als[s * HEADS];
        float2 ad2 = *(const float2*)&g_ald[d * HEADS];
        w2.x = __expf(leaky(as2.x + ad2.x));
        w2.y = __expf(leaky(as2.y + ad2.y));
    }
    ((float2*)g_wbuf)[j] = w2;
}

// ---------------- aggregation: one warp per node (fp16 gathers) ---------------
// Each lane owns 4 channels (uint2 = 2x half2 = 8 B; full row = 256 B).
// fp32 accumulation; writes fp32 (pool) + fp16 (next GEMM input).
__global__ void agg_kernel(const float* __restrict__ bias) {
    int n = (blockIdx.x * blockDim.x + threadIdx.x) >> 5;
    int lane = threadIdx.x & 31;
    if (n >= NN) return;
    int head = lane >> 4;                 // lanes 0-15: head0, 16-31: head1

    int o0 = g_off[n], o1 = g_off[n + 1];

    float4 acc = make_float4(0.f, 0.f, 0.f, 0.f);
    float denom = 0.f;

    int sj = (o0 < o1) ? __ldg(&g_srcidx[o0]) : 0;
    for (int j = o0; j < o1; j++) {
        int s = sj;
        if (j + 1 < o1) sj = __ldg(&g_srcidx[j + 1]);          // prefetch
        float2 w2 = __ldg(((const float2*)g_wbuf) + j);        // streaming
        float w = (head == 0) ? w2.x : w2.y;
        uint2 u = __ldg(((const uint2*)(g_h + (size_t)s * (D / 2))) + lane);
        float2 f01 = __half22float2(*(__half2*)&u.x);
        float2 f23 = __half22float2(*(__half2*)&u.y);
        acc.x += w * f01.x; acc.y += w * f01.y; acc.z += w * f23.x; acc.w += w * f23.y;
        denom += w;
    }
    {   // self-loop
        float2 a2 = *(const float2*)&g_als[n * HEADS];
        float2 d2 = *(const float2*)&g_ald[n * HEADS];
        float e = (head == 0) ? leaky(a2.x + d2.x) : leaky(a2.y + d2.y);
        float w = __expf(e);
        uint2 u = ((const uint2*)(g_h + (size_t)n * (D / 2)))[lane];
        float2 f01 = __half22float2(*(__half2*)&u.x);
        float2 f23 = __half22float2(*(__half2*)&u.y);
        acc.x += w * f01.x; acc.y += w * f01.y; acc.z += w * f23.x; acc.w += w * f23.y;
        denom += w;
    }

    float inv = 1.f / denom;
    float4 bb = __ldg(((const float4*)bias) + lane);
    float v0 = acc.x * inv + bb.x;
    float v1 = acc.y * inv + bb.y;
    float v2 = acc.z * inv + bb.z;
    float v3 = acc.w * inv + bb.w;
    float4 outv;
    outv.x = v0 > 0.f ? v0 : expm1f(v0);
    outv.y = v1 > 0.f ? v1 : expm1f(v1);
    outv.z = v2 > 0.f ? v2 : expm1f(v2);
    outv.w = v3 > 0.f ? v3 : expm1f(v3);
    ((float4*)(g_feat + (size_t)n * D))[lane] = outv;
    __half2 p0 = __floats2half2_rn(outv.x, outv.y);
    __half2 p1 = __floats2half2_rn(outv.z, outv.w);
    uint2 uo = make_uint2(*(unsigned*)&p0, *(unsigned*)&p1);
    *(uint2*)&g_featH[(size_t)n * D + lane * 4] = uo;
}

// ---------------- mean pool: batch is SORTED -> run accumulation --------------
#define PCH 32
__global__ void pool_kernel(const int* __restrict__ batch) {
    int c = threadIdx.x;                    // 0..127 channel
    int b0 = blockIdx.x * PCH;
    if (b0 >= NN) return;
    int nend = b0 + PCH; if (nend > NN) nend = NN;
    int curg = __ldg(&batch[b0]);
    float racc = 0.f;
    int rcnt = 0;
    for (int nidx = b0; nidx < nend; nidx++) {
        int g = __ldg(&batch[nidx]);
        if (g != curg) {
            if ((unsigned)curg < GG) {
                atomicAdd(&g_pool[curg * D + c], racc);
                if (c == 0) atomicAdd(&g_cnt[curg], rcnt);
            }
            racc = 0.f; rcnt = 0; curg = g;
        }
        racc += g_feat[(size_t)nidx * D + c];
        rcnt++;
    }
    if ((unsigned)curg < GG) {
        atomicAdd(&g_pool[curg * D + c], racc);
        if (c == 0) atomicAdd(&g_cnt[curg], rcnt);
    }
}

// ---------------- head MLP ---------------------------------------------------
__global__ void head_kernel(const float* __restrict__ l1w, const float* __restrict__ l1b,
                            const float* __restrict__ l2w, const float* __restrict__ l2b,
                            float* __restrict__ out) {
    int gid = blockIdx.x;    // 0..63
    int t = threadIdx.x;     // 0..63
    __shared__ float mean[D];
    __shared__ float z[HID];
    float invc = 1.f / fmaxf((float)g_cnt[gid], 1.f);
    mean[t]      = g_pool[gid * D + t] * invc;
    mean[t + 64] = g_pool[gid * D + 64 + t] * invc;
    __syncthreads();
    float acc = l1b[t];
    for (int k = 0; k < D; k++) acc += mean[k] * l1w[k * HID + t];
    z[t] = fmaxf(acc, 0.f);
    __syncthreads();
    if (t < OUTD) {
        float o = l2b[t];
        for (int k = 0; k < HID; k++) o += z[k] * l2w[k * OUTD + t];
        out[gid * OUTD + t] = o;
    }
}

// ---------------- driver ------------------------------------------------------
extern "C" void kernel_launch(void* const* d_in, const int* in_sizes, int n_in,
                              void* d_out, int out_size) {
    const float* x     = (const float*)d_in[0];
    const int*   ei    = (const int*)d_in[1];     // int64 in reference -> int32 on device
    const int*   batch = (const int*)d_in[2];     // int64 in reference -> int32 on device
    const float* Wl[3] = { (const float*)d_in[3],  (const float*)d_in[7],  (const float*)d_in[11] };
    const float* As[3] = { (const float*)d_in[4],  (const float*)d_in[8],  (const float*)d_in[12] };
    const float* Ad[3] = { (const float*)d_in[5],  (const float*)d_in[9],  (const float*)d_in[13] };
    const float* Bl[3] = { (const float*)d_in[6],  (const float*)d_in[10], (const float*)d_in[14] };
    const float* l1w = (const float*)d_in[15];
    const float* l1b = (const float*)d_in[16];
    const float* l2w = (const float*)d_in[17];
    const float* l2b = (const float*)d_in[18];
    float* out = (float*)d_out;

    const int weight_blocks = (EE + 255) / 256;
    const int agg_blocks    = (NN * 32 + 255) / 256;

    // prep: W fp16 transposes + x fp16 convert + CSR degree count (one launch)
    prep_kernel<<<3 + XCONV_BLOCKS + COUNT_BLOCKS, 256>>>(x, Wl[0], Wl[1], Wl[2], ei);
    bsum_kernel<<<NB, SB>>>();
    bscan_kernel<<<1, SB>>>();
    offs_kernel<<<NB, SB>>>();
    scatter_kernel<<<(EE + 255) / 256, 256>>>(ei);

    for (int l = 0; l < 3; l++) {
        gemm_mma_kernel<<<GEMM_BLOCKS, 256>>>(As[l], Ad[l], l);
        weight_kernel<<<weight_blocks, 256>>>();
        agg_kernel<<<agg_blocks, 256>>>(Bl[l]);
    }

    pool_kernel<<<(NN + PCH - 1) / PCH, D>>>(batch);
    head_kernel<<<GG, HID>>>(l1w, l1b, l2w, l2b, out);
}